// round 10
// baseline (speedup 1.0000x reference)
#include <cuda_runtime.h>
#include <math.h>

// Canny edge detection: 16 images of 1024x1024 (green channel of NCHW input).
// Pipeline: 5x5 Gaussian blur -> Sobel -> |grad| + per-image max -> NMS ->
// double threshold -> hysteresis (union-find connected components) -> output.
// Conv numerics: REVERSED row-major sequential FFMA (kernel-flip convolution
// order, taps 24->0). Weights numpy-bit-emulated. CR atan2 rescue at
// direction boundaries (proven harmless, kept).

#define BATCH 16
#define H 1024
#define W 1024
#define NPIX (H * W)
#define TOT (BATCH * NPIX)
#define SOBEL_BLOCKS 65536   // (32,128,16) grid of (32,8) blocks

// Scratch (static __device__ — no runtime allocation allowed)
__device__ float         g_blur[TOT];
__device__ float         g_mag[TOT];
__device__ unsigned char g_dir[TOT];
__device__ unsigned char g_ws[TOT];       // bit0 = weak, bit1 = strong
__device__ int           g_label[TOT];    // union-find parent
__device__ unsigned char g_rootflag[TOT]; // component-has-strong flag (indexed by root)
__device__ float         g_blockmax[SOBEL_BLOCKS];
__device__ float         g_max[BATCH];
__device__ float         g_w25[25];       // numpy-bit-exact gaussian weights

// ---------------------------------------------------------------------------
// K0: zero root flags + (thread 0) build gaussian weights exactly as numpy:
//   g = float32(exp(-ax^2/2)); k = outer(g,g); k /= k.sum() (numpy pairwise sum)
__global__ void k_init() {
    int i = blockIdx.x * blockDim.x + threadIdx.x;
    if (i < TOT / 16) {
        reinterpret_cast<uint4*>(g_rootflag)[i] = make_uint4(0u, 0u, 0u, 0u);
    }
    if (blockIdx.x == 0 && threadIdx.x == 0) {
        float gf[5];
#pragma unroll
        for (int t = 0; t < 5; t++) {
            double ax = (double)(t - 2);
            gf[t] = (float)exp(-0.5 * ax * ax);   // CR float exp
        }
        float p[25];
#pragma unroll
        for (int r = 0; r < 5; r++)
#pragma unroll
            for (int c = 0; c < 5; c++)
                p[r * 5 + c] = __fmul_rn(gf[r], gf[c]);
        // numpy pairwise_sum, n=25: 8 accumulators over 24 elems + remainder
        float acc8[8];
#pragma unroll
        for (int j = 0; j < 8; j++) acc8[j] = p[j];
#pragma unroll
        for (int j = 0; j < 8; j++) acc8[j] = __fadd_rn(acc8[j], p[8 + j]);
#pragma unroll
        for (int j = 0; j < 8; j++) acc8[j] = __fadd_rn(acc8[j], p[16 + j]);
        float s01 = __fadd_rn(acc8[0], acc8[1]);
        float s23 = __fadd_rn(acc8[2], acc8[3]);
        float s45 = __fadd_rn(acc8[4], acc8[5]);
        float s67 = __fadd_rn(acc8[6], acc8[7]);
        float res = __fadd_rn(__fadd_rn(s01, s23), __fadd_rn(s45, s67));
        res = __fadd_rn(res, p[24]);
#pragma unroll
        for (int k = 0; k < 25; k++) g_w25[k] = __fdiv_rn(p[k], res);
    }
}

// ---------------------------------------------------------------------------
// K1: 5x5 Gaussian blur (zero padding SAME), REVERSED row-major FFMA (24->0)
__global__ __launch_bounds__(256) void k_blur(const float* __restrict__ x) {
    int px = blockIdx.x * 32 + threadIdx.x;
    int py = blockIdx.y * 8 + threadIdx.y;
    int b  = blockIdx.z;
    const float* __restrict__ img = x + ((size_t)b * 3 + 1) * NPIX;  // green channel

    float w[25];
#pragma unroll
    for (int k = 0; k < 25; k++) w[k] = g_w25[k];

    float acc = 0.0f;
#pragma unroll
    for (int ky = 4; ky >= 0; ky--) {
        int sy = py + ky - 2;
        bool yok = (sy >= 0 && sy < H);
#pragma unroll
        for (int kx = 4; kx >= 0; kx--) {
            int sx = px + kx - 2;
            float v = (yok && sx >= 0 && sx < W) ? __ldg(img + sy * W + sx) : 0.0f;
            acc = __fmaf_rn(w[ky * 5 + kx], v, acc);
        }
    }
    g_blur[(size_t)b * NPIX + py * W + px] = acc;
}

// ---------------------------------------------------------------------------
// Direction with CR-atan2 rescue near the 22.5-degree decision boundaries.
__device__ __forceinline__ unsigned char direction_of(float gx, float gy) {
    float deg = __fmul_rn(atan2f(gy, gx), 57.29577951308232f);
    float r = fmodf(deg, 180.0f);
    if (r < 0.0f) r = __fadd_rn(r, 180.0f);

    float d0 = fabsf(r - 22.5f);
    float d1 = fabsf(r - 67.5f);
    float d2 = fabsf(r - 112.5f);
    float d3 = fabsf(r - 157.5f);
    float dmin = fminf(fminf(d0, d1), fminf(d2, d3));
    if (dmin < 2e-4f) {
        float at = (float)atan2((double)gy, (double)gx);
        deg = __fmul_rn(at, 57.29577951308232f);
        r = fmodf(deg, 180.0f);
        if (r < 0.0f) r = __fadd_rn(r, 180.0f);
    }

    if (r < 22.5f || r >= 157.5f) return 0;
    else if (r < 67.5f)           return 1;
    else if (r < 112.5f)          return 2;
    else                          return 3;
}

// ---------------------------------------------------------------------------
// K2: Sobel -> magnitude, direction, per-block max.
//     REVERSED row-major sequential FFMA (taps 8->0; zero taps skipped).
__global__ __launch_bounds__(256) void k_sobel() {
    int x = blockIdx.x * 32 + threadIdx.x;
    int y = blockIdx.y * 8 + threadIdx.y;
    int b = blockIdx.z;
    const float* __restrict__ img = g_blur + (size_t)b * NPIX;

    float a[3][3];
#pragma unroll
    for (int i = 0; i < 3; i++) {
#pragma unroll
        for (int j = 0; j < 3; j++) {
            int yy = y + i - 1, xx = x + j - 1;
            a[i][j] = (yy >= 0 && yy < H && xx >= 0 && xx < W) ? img[yy * W + xx] : 0.0f;
        }
    }
    // gx reversed row-major: (2,2)+1, (2,0)-1, (1,2)+2, (1,0)-2, (0,2)+1, (0,0)-1
    float gx = 0.0f;
    gx = __fmaf_rn( 1.0f, a[2][2], gx);
    gx = __fmaf_rn(-1.0f, a[2][0], gx);
    gx = __fmaf_rn( 2.0f, a[1][2], gx);
    gx = __fmaf_rn(-2.0f, a[1][0], gx);
    gx = __fmaf_rn( 1.0f, a[0][2], gx);
    gx = __fmaf_rn(-1.0f, a[0][0], gx);

    // gy reversed row-major: (2,2)+1, (2,1)+2, (2,0)+1, (0,2)-1, (0,1)-2, (0,0)-1
    float gy = 0.0f;
    gy = __fmaf_rn( 1.0f, a[2][2], gy);
    gy = __fmaf_rn( 2.0f, a[2][1], gy);
    gy = __fmaf_rn( 1.0f, a[2][0], gy);
    gy = __fmaf_rn(-1.0f, a[0][2], gy);
    gy = __fmaf_rn(-2.0f, a[0][1], gy);
    gy = __fmaf_rn(-1.0f, a[0][0], gy);

    // mag: separate-rounded elementwise ops; correctly-rounded sqrt
    float m2  = __fadd_rn(__fadd_rn(__fmul_rn(gx, gx), __fmul_rn(gy, gy)), 1e-12f);
    float mag = __fsqrt_rn(m2);

    size_t idx = (size_t)b * NPIX + y * W + x;
    g_mag[idx] = mag;
    g_dir[idx] = direction_of(gx, gy);

    // block max reduction (exact)
    __shared__ float smax[256];
    int t = threadIdx.y * 32 + threadIdx.x;
    smax[t] = mag;
    __syncthreads();
#pragma unroll
    for (int s = 128; s > 0; s >>= 1) {
        if (t < s) smax[t] = fmaxf(smax[t], smax[t + s]);
        __syncthreads();
    }
    if (t == 0) {
        g_blockmax[(blockIdx.z * gridDim.y + blockIdx.y) * gridDim.x + blockIdx.x] = smax[0];
    }
}

// ---------------------------------------------------------------------------
// K3: reduce 4096 block maxima per image -> g_max[b]
__global__ __launch_bounds__(256) void k_redmax() {
    int b = blockIdx.x;
    float m = 0.0f;
    for (int i = threadIdx.x; i < 4096; i += 256) {
        m = fmaxf(m, g_blockmax[b * 4096 + i]);
    }
    __shared__ float smax[256];
    smax[threadIdx.x] = m;
    __syncthreads();
#pragma unroll
    for (int s = 128; s > 0; s >>= 1) {
        if (threadIdx.x < s) smax[threadIdx.x] = fmaxf(smax[threadIdx.x], smax[threadIdx.x + s]);
        __syncthreads();
    }
    if (threadIdx.x == 0) g_max[b] = smax[0];
}

// ---------------------------------------------------------------------------
// K4: NMS + double threshold; init union-find labels
__global__ __launch_bounds__(256) void k_nms(const float* __restrict__ lowp,
                                             const float* __restrict__ highp) {
    int x = blockIdx.x * 32 + threadIdx.x;
    int y = blockIdx.y * 8 + threadIdx.y;
    int b = blockIdx.z;
    const float* __restrict__ mg = g_mag + (size_t)b * NPIX;

    float denom = __fadd_rn(g_max[b], 1e-12f);
    float low  = __ldg(lowp);
    float high = __ldg(highp);

    size_t idx = (size_t)b * NPIX + y * W + x;
    float m = mg[y * W + x];
    int   d = g_dir[idx];

    auto nb = [&](int yy, int xx) -> float {
        return (yy >= 0 && yy < H && xx >= 0 && xx < W) ? mg[yy * W + xx] : 0.0f;
    };

    float n1, n2;
    if (d == 0)      { n1 = nb(y,     x + 1); n2 = nb(y,     x - 1); }
    else if (d == 1) { n1 = nb(y - 1, x + 1); n2 = nb(y + 1, x - 1); }
    else if (d == 2) { n1 = nb(y - 1, x);     n2 = nb(y + 1, x);     }
    else             { n1 = nb(y - 1, x - 1); n2 = nb(y + 1, x + 1); }

    // reference order: normalize first (IEEE div), then compare
    float mn  = __fdiv_rn(m,  denom);
    float n1n = __fdiv_rn(n1, denom);
    float n2n = __fdiv_rn(n2, denom);
    float nms = (mn >= n1n && mn >= n2n) ? mn : 0.0f;

    unsigned char ws = 0;
    if (nms >= low)  ws |= 1;
    if (nms >= high) ws |= 2;

    g_ws[idx]    = ws;
    g_label[idx] = (int)idx;
}

// ---------------------------------------------------------------------------
// Lock-free union-find (min-root ordering)
__device__ __forceinline__ int uf_find(int i) {
    volatile int* L = g_label;
    while (true) {
        int p = L[i];
        if (p == i) return i;
        int gp = L[p];
        if (gp == p) return p;
        g_label[i] = gp;   // path halving (benign race)
        i = gp;
    }
}

__device__ __forceinline__ void uf_union(int a, int b) {
    while (true) {
        a = uf_find(a);
        b = uf_find(b);
        if (a == b) return;
        if (a > b) { int t = a; a = b; b = t; }
        int old = atomicCAS(&g_label[b], b, a);
        if (old == b) return;
        b = old;
    }
}

// K5: merge weak pixels with weak 8-neighbors (E, SW, S, SE covers all pairs)
__global__ __launch_bounds__(256) void k_union() {
    int x = blockIdx.x * 32 + threadIdx.x;
    int y = blockIdx.y * 8 + threadIdx.y;
    int b = blockIdx.z;
    int base = b * NPIX;
    int i = base + y * W + x;
    if (!(g_ws[i] & 1)) return;

    if (x + 1 < W             && (g_ws[i + 1]         & 1)) uf_union(i, i + 1);
    if (y + 1 < H) {
        int j = i + W;
        if (                      (g_ws[j]     & 1)) uf_union(i, j);
        if (x - 1 >= 0         && (g_ws[j - 1] & 1)) uf_union(i, j - 1);
        if (x + 1 < W          && (g_ws[j + 1] & 1)) uf_union(i, j + 1);
    }
}

// K6: mark components containing a strong pixel
__global__ __launch_bounds__(256) void k_mark() {
    int i = blockIdx.x * blockDim.x + threadIdx.x;
    if (i >= TOT) return;
    if (g_ws[i] & 2) {
        g_rootflag[uf_find(i)] = 1;
    }
}

// K7: final output = 50 * (edge - threshold)
__global__ __launch_bounds__(256) void k_out(float* __restrict__ out,
                                             const float* __restrict__ thrp) {
    int i = blockIdx.x * blockDim.x + threadIdx.x;
    if (i >= TOT) return;
    float thr = __ldg(thrp);
    float e = 0.0f;
    if (g_ws[i] & 1) {
        if (g_rootflag[uf_find(i)]) e = 1.0f;
    }
    out[i] = __fmul_rn(50.0f, __fadd_rn(e, -thr));
}

// ---------------------------------------------------------------------------
extern "C" void kernel_launch(void* const* d_in, const int* in_sizes, int n_in,
                              void* d_out, int out_size) {
    const float* x     = (const float*)d_in[0];
    const float* thr   = (const float*)d_in[1];
    const float* low   = (const float*)d_in[2];
    const float* high  = (const float*)d_in[3];
    float*       out   = (float*)d_out;

    dim3 blk(32, 8);
    dim3 grd(W / 32, H / 8, BATCH);   // (32, 128, 16)

    k_init<<<(TOT / 16 + 255) / 256, 256>>>();
    k_blur<<<grd, blk>>>(x);
    k_sobel<<<grd, blk>>>();
    k_redmax<<<BATCH, 256>>>();
    k_nms<<<grd, blk>>>(low, high);
    k_union<<<grd, blk>>>();
    k_mark<<<(TOT + 255) / 256, 256>>>();
    k_out<<<(TOT + 255) / 256, 256>>>(out, thr);
}

// round 12
// speedup vs baseline: 1.2329x; 1.2329x over previous
#include <cuda_runtime.h>
#include <math.h>

// Canny edge detection: 16 images of 1024x1024 (green channel of NCHW input).
// Blur -> Sobel -> mag/max -> NMS -> hysteresis (hierarchical CCL) -> output.
// Conv numerics: REVERSED row-major sequential FFMA (proven bit-match, R10).
// Hysteresis: tile-local shared-memory union-find + cross-tile border merge +
// flatten/mark pass (replaces whole-image global UF).

#define BATCH 16
#define H 1024
#define W 1024
#define NPIX (H * W)
#define TOT (BATCH * NPIX)
#define SOBEL_BLOCKS 65536   // (32,128,16) grid of (32,8) blocks

__device__ float         g_blur[TOT];
__device__ float         g_mag[TOT];
__device__ unsigned char g_dir[TOT];
__device__ unsigned char g_ws[TOT];       // bit0 = weak, bit1 = strong
__device__ int           g_label[TOT];    // union-find parent (weak pixels only)
__device__ unsigned char g_rootflag[TOT]; // component-has-strong flag (by root)
__device__ float         g_blockmax[SOBEL_BLOCKS];
__device__ float         g_max[BATCH];
__device__ float         g_w25[25];       // numpy-bit-exact gaussian weights

// ---------------------------------------------------------------------------
// K0: zero root flags + (thread 0) build gaussian weights exactly as numpy.
__global__ void k_init() {
    int i = blockIdx.x * blockDim.x + threadIdx.x;
    if (i < TOT / 16) {
        reinterpret_cast<uint4*>(g_rootflag)[i] = make_uint4(0u, 0u, 0u, 0u);
    }
    if (blockIdx.x == 0 && threadIdx.x == 0) {
        float gf[5];
#pragma unroll
        for (int t = 0; t < 5; t++) {
            double ax = (double)(t - 2);
            gf[t] = (float)exp(-0.5 * ax * ax);
        }
        float p[25];
#pragma unroll
        for (int r = 0; r < 5; r++)
#pragma unroll
            for (int c = 0; c < 5; c++)
                p[r * 5 + c] = __fmul_rn(gf[r], gf[c]);
        float acc8[8];
#pragma unroll
        for (int j = 0; j < 8; j++) acc8[j] = p[j];
#pragma unroll
        for (int j = 0; j < 8; j++) acc8[j] = __fadd_rn(acc8[j], p[8 + j]);
#pragma unroll
        for (int j = 0; j < 8; j++) acc8[j] = __fadd_rn(acc8[j], p[16 + j]);
        float s01 = __fadd_rn(acc8[0], acc8[1]);
        float s23 = __fadd_rn(acc8[2], acc8[3]);
        float s45 = __fadd_rn(acc8[4], acc8[5]);
        float s67 = __fadd_rn(acc8[6], acc8[7]);
        float res = __fadd_rn(__fadd_rn(s01, s23), __fadd_rn(s45, s67));
        res = __fadd_rn(res, p[24]);
#pragma unroll
        for (int k = 0; k < 25; k++) g_w25[k] = __fdiv_rn(p[k], res);
    }
}

// ---------------------------------------------------------------------------
// K1: 5x5 Gaussian blur, REVERSED row-major FFMA (bit-matches reference)
__global__ __launch_bounds__(256) void k_blur(const float* __restrict__ x) {
    int px = blockIdx.x * 32 + threadIdx.x;
    int py = blockIdx.y * 8 + threadIdx.y;
    int b  = blockIdx.z;
    const float* __restrict__ img = x + ((size_t)b * 3 + 1) * NPIX;

    float w[25];
#pragma unroll
    for (int k = 0; k < 25; k++) w[k] = g_w25[k];

    float acc = 0.0f;
#pragma unroll
    for (int ky = 4; ky >= 0; ky--) {
        int sy = py + ky - 2;
        bool yok = (sy >= 0 && sy < H);
#pragma unroll
        for (int kx = 4; kx >= 0; kx--) {
            int sx = px + kx - 2;
            float v = (yok && sx >= 0 && sx < W) ? __ldg(img + sy * W + sx) : 0.0f;
            acc = __fmaf_rn(w[ky * 5 + kx], v, acc);
        }
    }
    g_blur[(size_t)b * NPIX + py * W + px] = acc;
}

// ---------------------------------------------------------------------------
__device__ __forceinline__ unsigned char direction_of(float gx, float gy) {
    float deg = __fmul_rn(atan2f(gy, gx), 57.29577951308232f);
    float r = fmodf(deg, 180.0f);
    if (r < 0.0f) r = __fadd_rn(r, 180.0f);

    float d0 = fabsf(r - 22.5f);
    float d1 = fabsf(r - 67.5f);
    float d2 = fabsf(r - 112.5f);
    float d3 = fabsf(r - 157.5f);
    float dmin = fminf(fminf(d0, d1), fminf(d2, d3));
    if (dmin < 2e-4f) {
        float at = (float)atan2((double)gy, (double)gx);
        deg = __fmul_rn(at, 57.29577951308232f);
        r = fmodf(deg, 180.0f);
        if (r < 0.0f) r = __fadd_rn(r, 180.0f);
    }

    if (r < 22.5f || r >= 157.5f) return 0;
    else if (r < 67.5f)           return 1;
    else if (r < 112.5f)          return 2;
    else                          return 3;
}

// ---------------------------------------------------------------------------
// K2: Sobel (reversed row-major FFMA) -> magnitude, direction, block max
__global__ __launch_bounds__(256) void k_sobel() {
    int x = blockIdx.x * 32 + threadIdx.x;
    int y = blockIdx.y * 8 + threadIdx.y;
    int b = blockIdx.z;
    const float* __restrict__ img = g_blur + (size_t)b * NPIX;

    float a[3][3];
#pragma unroll
    for (int i = 0; i < 3; i++) {
#pragma unroll
        for (int j = 0; j < 3; j++) {
            int yy = y + i - 1, xx = x + j - 1;
            a[i][j] = (yy >= 0 && yy < H && xx >= 0 && xx < W) ? img[yy * W + xx] : 0.0f;
        }
    }
    float gx = 0.0f;
    gx = __fmaf_rn( 1.0f, a[2][2], gx);
    gx = __fmaf_rn(-1.0f, a[2][0], gx);
    gx = __fmaf_rn( 2.0f, a[1][2], gx);
    gx = __fmaf_rn(-2.0f, a[1][0], gx);
    gx = __fmaf_rn( 1.0f, a[0][2], gx);
    gx = __fmaf_rn(-1.0f, a[0][0], gx);

    float gy = 0.0f;
    gy = __fmaf_rn( 1.0f, a[2][2], gy);
    gy = __fmaf_rn( 2.0f, a[2][1], gy);
    gy = __fmaf_rn( 1.0f, a[2][0], gy);
    gy = __fmaf_rn(-1.0f, a[0][2], gy);
    gy = __fmaf_rn(-2.0f, a[0][1], gy);
    gy = __fmaf_rn(-1.0f, a[0][0], gy);

    float m2  = __fadd_rn(__fadd_rn(__fmul_rn(gx, gx), __fmul_rn(gy, gy)), 1e-12f);
    float mag = __fsqrt_rn(m2);

    size_t idx = (size_t)b * NPIX + y * W + x;
    g_mag[idx] = mag;
    g_dir[idx] = direction_of(gx, gy);

    __shared__ float smax[256];
    int t = threadIdx.y * 32 + threadIdx.x;
    smax[t] = mag;
    __syncthreads();
#pragma unroll
    for (int s = 128; s > 0; s >>= 1) {
        if (t < s) smax[t] = fmaxf(smax[t], smax[t + s]);
        __syncthreads();
    }
    if (t == 0) {
        g_blockmax[(blockIdx.z * gridDim.y + blockIdx.y) * gridDim.x + blockIdx.x] = smax[0];
    }
}

// ---------------------------------------------------------------------------
// K3: reduce 4096 block maxima per image
__global__ __launch_bounds__(256) void k_redmax() {
    int b = blockIdx.x;
    float m = 0.0f;
    for (int i = threadIdx.x; i < 4096; i += 256) {
        m = fmaxf(m, g_blockmax[b * 4096 + i]);
    }
    __shared__ float smax[256];
    smax[threadIdx.x] = m;
    __syncthreads();
#pragma unroll
    for (int s = 128; s > 0; s >>= 1) {
        if (threadIdx.x < s) smax[threadIdx.x] = fmaxf(smax[threadIdx.x], smax[threadIdx.x + s]);
        __syncthreads();
    }
    if (threadIdx.x == 0) g_max[b] = smax[0];
}

// ---------------------------------------------------------------------------
// K4: NMS + double threshold (no label init — labels only written for weak)
__global__ __launch_bounds__(256) void k_nms(const float* __restrict__ lowp,
                                             const float* __restrict__ highp) {
    int x = blockIdx.x * 32 + threadIdx.x;
    int y = blockIdx.y * 8 + threadIdx.y;
    int b = blockIdx.z;
    const float* __restrict__ mg = g_mag + (size_t)b * NPIX;

    float denom = __fadd_rn(g_max[b], 1e-12f);
    float low  = __ldg(lowp);
    float high = __ldg(highp);

    size_t idx = (size_t)b * NPIX + y * W + x;
    float m = mg[y * W + x];
    int   d = g_dir[idx];

    auto nb = [&](int yy, int xx) -> float {
        return (yy >= 0 && yy < H && xx >= 0 && xx < W) ? mg[yy * W + xx] : 0.0f;
    };

    float n1, n2;
    if (d == 0)      { n1 = nb(y,     x + 1); n2 = nb(y,     x - 1); }
    else if (d == 1) { n1 = nb(y - 1, x + 1); n2 = nb(y + 1, x - 1); }
    else if (d == 2) { n1 = nb(y - 1, x);     n2 = nb(y + 1, x);     }
    else             { n1 = nb(y - 1, x - 1); n2 = nb(y + 1, x + 1); }

    float mn  = __fdiv_rn(m,  denom);
    float n1n = __fdiv_rn(n1, denom);
    float n2n = __fdiv_rn(n2, denom);
    float nms = (mn >= n1n && mn >= n2n) ? mn : 0.0f;

    unsigned char ws = 0;
    if (nms >= low)  ws |= 1;
    if (nms >= high) ws |= 2;

    g_ws[idx] = ws;
}

// ---------------------------------------------------------------------------
// Shared-memory union-find (tile-local, min-root)
__device__ __forceinline__ int lfind(int* lp, int i) {
    volatile int* L = lp;
    while (true) {
        int p = L[i];
        if (p == i) return i;
        int gp = L[p];
        if (gp == p) return p;
        lp[i] = gp;
        i = gp;
    }
}
__device__ __forceinline__ void lunion(int* lp, int a, int b) {
    while (true) {
        a = lfind(lp, a);
        b = lfind(lp, b);
        if (a == b) return;
        if (a > b) { int t = a; a = b; b = t; }
        int old = atomicCAS(&lp[b], b, a);
        if (old == b) return;
        b = old;
    }
}

// Global union-find (min-root)
__device__ __forceinline__ int uf_find(int i) {
    volatile int* L = g_label;
    while (true) {
        int p = L[i];
        if (p == i) return i;
        int gp = L[p];
        if (gp == p) return p;
        g_label[i] = gp;
        i = gp;
    }
}
__device__ __forceinline__ int uf_find_ro(int i) {   // read-only (no halving)
    volatile int* L = g_label;
    while (true) {
        int p = L[i];
        if (p == i) return i;
        i = p;
    }
}
__device__ __forceinline__ void uf_union(int a, int b) {
    while (true) {
        a = uf_find(a);
        b = uf_find(b);
        if (a == b) return;
        if (a > b) { int t = a; a = b; b = t; }
        int old = atomicCAS(&g_label[b], b, a);
        if (old == b) return;
        b = old;
    }
}

// ---------------------------------------------------------------------------
// K5: tile-local CCL (32x32 tile, shared-memory UF), write tile-root labels
__global__ __launch_bounds__(1024) void k_local() {
    __shared__ int lp[1024];
    int lx = threadIdx.x, ly = threadIdx.y;
    int l  = ly * 32 + lx;
    int x  = blockIdx.x * 32 + lx;
    int y  = blockIdx.y * 32 + ly;
    int b  = blockIdx.z;
    int gi = b * NPIX + y * W + x;

    bool w = (g_ws[gi] & 1);
    lp[l] = l;
    __syncthreads();

    if (w) {
        if (lx < 31 && (g_ws[gi + 1] & 1)) lunion(lp, l, l + 1);
        if (ly < 31) {
            if (          (g_ws[gi + W]     & 1)) lunion(lp, l, l + 32);
            if (lx > 0 && (g_ws[gi + W - 1] & 1)) lunion(lp, l, l + 31);
            if (lx < 31 && (g_ws[gi + W + 1] & 1)) lunion(lp, l, l + 33);
        }
    }
    __syncthreads();

    if (w) {
        int r  = lfind(lp, l);
        int rx = r & 31, ry = r >> 5;
        g_label[gi] = b * NPIX + (blockIdx.y * 32 + ry) * W + (blockIdx.x * 32 + rx);
    }
}

// ---------------------------------------------------------------------------
// K6: merge weak pairs crossing 32x32 tile boundaries (global UF)
__global__ __launch_bounds__(256) void k_border() {
    int i = blockIdx.x * blockDim.x + threadIdx.x;
    if (i >= TOT) return;
    if (!(g_ws[i] & 1)) return;

    int pi = i % NPIX;
    int x  = pi % W;
    int y  = pi / W;

    bool xe = ((x & 31) == 31);   // right tile edge
    bool x0 = ((x & 31) == 0);    // left tile edge
    bool ye = ((y & 31) == 31);   // bottom tile edge

    if (x < W - 1 && xe && (g_ws[i + 1] & 1)) uf_union(i, i + 1);
    if (y < H - 1) {
        if (ye            && (g_ws[i + W]     & 1)) uf_union(i, i + W);
        if (x > 0     && (ye || x0) && (g_ws[i + W - 1] & 1)) uf_union(i, i + W - 1);
        if (x < W - 1 && (ye || xe) && (g_ws[i + W + 1] & 1)) uf_union(i, i + W + 1);
    }
}

// ---------------------------------------------------------------------------
// K7: flatten weak labels to roots (read-only find) + mark strong components
__global__ __launch_bounds__(256) void k_flatmark() {
    int i = blockIdx.x * blockDim.x + threadIdx.x;
    if (i >= TOT) return;
    unsigned char ws = g_ws[i];
    if (ws & 1) {
        int r = uf_find_ro(i);
        g_label[i] = r;
        if (ws & 2) g_rootflag[r] = 1;
    }
}

// ---------------------------------------------------------------------------
// K8: output = 50 * (edge - threshold); labels are flattened roots
__global__ __launch_bounds__(256) void k_out(float* __restrict__ out,
                                             const float* __restrict__ thrp) {
    int i = blockIdx.x * blockDim.x + threadIdx.x;
    if (i >= TOT) return;
    float thr = __ldg(thrp);
    float e = 0.0f;
    if (g_ws[i] & 1) {
        if (g_rootflag[g_label[i]]) e = 1.0f;
    }
    out[i] = __fmul_rn(50.0f, __fadd_rn(e, -thr));
}

// ---------------------------------------------------------------------------
extern "C" void kernel_launch(void* const* d_in, const int* in_sizes, int n_in,
                              void* d_out, int out_size) {
    const float* x     = (const float*)d_in[0];
    const float* thr   = (const float*)d_in[1];
    const float* low   = (const float*)d_in[2];
    const float* high  = (const float*)d_in[3];
    float*       out   = (float*)d_out;

    dim3 blk(32, 8);
    dim3 grd(W / 32, H / 8, BATCH);     // (32, 128, 16)
    dim3 blk32(32, 32);
    dim3 grd32(W / 32, H / 32, BATCH);  // (32, 32, 16)

    k_init<<<(TOT / 16 + 255) / 256, 256>>>();
    k_blur<<<grd, blk>>>(x);
    k_sobel<<<grd, blk>>>();
    k_redmax<<<BATCH, 256>>>();
    k_nms<<<grd, blk>>>(low, high);
    k_local<<<grd32, blk32>>>();
    k_border<<<(TOT + 255) / 256, 256>>>();
    k_flatmark<<<(TOT + 255) / 256, 256>>>();
    k_out<<<(TOT + 255) / 256, 256>>>(out, thr);
}